// round 12
// baseline (speedup 1.0000x reference)
#include <cuda_runtime.h>
#include <cuda_bf16.h>
#include <stdint.h>

#define BATCH   8192
#define IN_DIM  2048
#define OUT_DIM 2048
#define DEPTH   5

// ---------------- device scratch (no allocs allowed) ----------------
// Two-level int8 quantization: plane 0 = q1 (coarse), plane 1 = q2 (fine, x254)
__device__ int8_t g_A8[2][(size_t)BATCH * IN_DIM];    // x rows, per-row scale g_sa
__device__ int8_t g_W8[2][(size_t)OUT_DIM * IN_DIM];  // W^T rows (n-major), per-n scale g_sb
__device__ float  g_sa[BATCH];                        // alpha_m = rowmax/127
__device__ float  g_sb[OUT_DIM];                      // beta_n
__device__ float  g_add[OUT_DIM];                     // bias + hd

// ---------------- PTX helpers (family-stable only) ----------------
__device__ __forceinline__ uint32_t smem_u32(const void* p) {
    uint32_t a;
    asm("{ .reg .u64 t; cvta.to.shared.u64 t, %1; cvt.u32.u64 %0, t; }" : "=r"(a) : "l"(p));
    return a;
}
__device__ __forceinline__ void cpa16(uint32_t s, const void* g) {
    asm volatile("cp.async.cg.shared.global [%0], [%1], 16;" :: "r"(s), "l"(g));
}
__device__ __forceinline__ void ldm4(uint32_t* r, uint32_t addr) {
    asm volatile("ldmatrix.sync.aligned.m8n8.x4.shared.b16 {%0,%1,%2,%3}, [%4];"
                 : "=r"(r[0]), "=r"(r[1]), "=r"(r[2]), "=r"(r[3]) : "r"(addr));
}
// s32 += s8 x s8, m16n8k32 (byte layout of operands identical to bf16 m16n8k16 ldmatrix)
__device__ __forceinline__ void mma_s8(int* c, const uint32_t* a, uint32_t b0, uint32_t b1) {
    asm volatile(
        "mma.sync.aligned.m16n8k32.row.col.s32.s8.s8.s32 "
        "{%0,%1,%2,%3}, {%4,%5,%6,%7}, {%8,%9}, {%0,%1,%2,%3};"
        : "+r"(c[0]), "+r"(c[1]), "+r"(c[2]), "+r"(c[3])
        : "r"(a[0]), "r"(a[1]), "r"(a[2]), "r"(a[3]), "r"(b0), "r"(b1));
}
__device__ __forceinline__ float tanh_apx(float x) {
    float y;
    asm("tanh.approx.f32 %0, %1;" : "=f"(y) : "f"(x));
    return y;
}
__device__ __forceinline__ int pack4(float a, float b, float c, float d) {
    int ia = __float2int_rn(a), ib = __float2int_rn(b);
    int ic = __float2int_rn(c), id = __float2int_rn(d);
    return (ia & 0xFF) | ((ib & 0xFF) << 8) | ((ic & 0xFF) << 16) | (id << 24);
}
#define SWZ(o) ((o) ^ (((o) >> 3) & 0x70))

// ---------------- prepass: quantize A (one warp per row) ----------------
__global__ void quant_a_kernel(const float* __restrict__ x) {
    const int wid = threadIdx.x >> 5, lane = threadIdx.x & 31;
    const int row = blockIdx.x * 8 + wid;
    const float4* xr = (const float4*)(x + (size_t)row * IN_DIM);
    float4 v[16];
    float m = 0.0f;
#pragma unroll
    for (int i = 0; i < 16; ++i) {
        v[i] = xr[lane + i * 32];
        m = fmaxf(m, fmaxf(fmaxf(fabsf(v[i].x), fabsf(v[i].y)),
                           fmaxf(fabsf(v[i].z), fabsf(v[i].w))));
    }
#pragma unroll
    for (int s = 16; s; s >>= 1) m = fmaxf(m, __shfl_xor_sync(0xffffffffu, m, s));
    m = fmaxf(m, 1e-20f);
    const float alpha = m * (1.0f / 127.0f);
    const float si = 127.0f / m;
    const float s2 = 254.0f / alpha;
    if (lane == 0) g_sa[row] = alpha;
    int* q1o = (int*)(g_A8[0] + (size_t)row * IN_DIM);
    int* q2o = (int*)(g_A8[1] + (size_t)row * IN_DIM);
#pragma unroll
    for (int i = 0; i < 16; ++i) {
        float q1x = rintf(v[i].x * si), q1y = rintf(v[i].y * si);
        float q1z = rintf(v[i].z * si), q1w = rintf(v[i].w * si);
        float rx = fmaf(-q1x, alpha, v[i].x), ry = fmaf(-q1y, alpha, v[i].y);
        float rz = fmaf(-q1z, alpha, v[i].z), rw = fmaf(-q1w, alpha, v[i].w);
        float q2x = fminf(127.f, fmaxf(-127.f, rx * s2));
        float q2y = fminf(127.f, fmaxf(-127.f, ry * s2));
        float q2z = fminf(127.f, fmaxf(-127.f, rz * s2));
        float q2w = fminf(127.f, fmaxf(-127.f, rw * s2));
        q1o[lane + i * 32] = pack4(q1x, q1y, q1z, q1w);
        q2o[lane + i * 32] = pack4(q2x, q2y, q2z, q2w);
    }
}

// ---------------- prepass: W column max (= W^T row max) ----------------
__global__ void colmax_w_kernel(const float* __restrict__ W) {
    const int n = blockIdx.x * blockDim.x + threadIdx.x;
    float m = 0.0f;
    for (int k = 0; k < IN_DIM; ++k)
        m = fmaxf(m, fabsf(W[(size_t)k * OUT_DIM + n]));
    g_sb[n] = fmaxf(m, 1e-20f) * (1.0f / 127.0f);
}

// ---------------- prepass: transpose + quantize W ----------------
// tile: 32 n x 128 k. Output rows are W^T (n-major, k contiguous int8).
__global__ void quant_w_kernel(const float* __restrict__ W) {
    __shared__ float t[128][33];
    const int bn = blockIdx.x * 32, bk = blockIdx.y * 128;
    const int tid = threadIdx.x;
    // load: each warp reads 32 consecutive n for rows of k (coalesced 128B)
    {
        const int ln = tid & 31, kk = tid >> 5;   // 8 k-rows per pass
#pragma unroll
        for (int i = 0; i < 16; ++i)
            t[kk + i * 8][ln] = W[(size_t)(bk + kk + i * 8) * OUT_DIM + bn + ln];
    }
    __syncthreads();
    // write: thread -> (n = tid/8, k16 group = tid%8): 4 int32 (16 int8) each
    const int n = bn + (tid >> 3);
    const int kg = (tid & 7) * 16;
    const float beta = g_sb[n];
    const float si = 1.0f / beta;
    const float s2 = 254.0f * si;
    int* q1o = (int*)(g_W8[0] + (size_t)n * IN_DIM + bk + kg);
    int* q2o = (int*)(g_W8[1] + (size_t)n * IN_DIM + bk + kg);
#pragma unroll
    for (int j = 0; j < 4; ++j) {
        float q1[4], q2[4];
#pragma unroll
        for (int e = 0; e < 4; ++e) {
            float v = t[kg + j * 4 + e][tid >> 3];
            q1[e] = rintf(v * si);
            float r = fmaf(-q1[e], beta, v);
            q2[e] = fminf(127.f, fmaxf(-127.f, r * s2));
        }
        q1o[j] = pack4(q1[0], q1[1], q1[2], q1[3]);
        q2o[j] = pack4(q2[0], q2[1], q2[2], q2[3]);
    }
}

__global__ void hd_bias_kernel(const float* __restrict__ hdw, const float* __restrict__ bias) {
    int o = blockIdx.x * blockDim.x + threadIdx.x;
    if (o < OUT_DIM) {
        float p = 1.0f;
#pragma unroll
        for (int d = 0; d < DEPTH; ++d)
            p *= cosf(hdw[(size_t)d * IN_DIM * OUT_DIM + (size_t)o * OUT_DIM]);
        g_add[o] = bias[o] + p * p * (1.0f / (float)IN_DIM);
    }
}

// ---------------- int8 IMMA GEMM ----------------
// CTA tile M=128 x N=256, chunk = 128 int8 k-elems (128B rows, SW128).
// Passes: chunks 0-15 = q1.p1 (S1, spilled to smem as fp32), 16-31 = q1.p2,
// 32-47 = q2.p1 (S2, shared int32 acc, factor 1/254).
// 8 warps (2m x 4n), warp tile 64x64, fragment double-buffered, 2-stage cp.async.
#define A_BYTES  (128 * 128)                     // 16 KB
#define B_BYTES  (256 * 128)                     // 32 KB
#define STG_B    (A_BYTES + B_BYTES)             // 48 KB
#define NCHUNK   48
#define SPILL_OFF (2 * STG_B)                    // 128 KB fp32 spill after stages

__device__ __forceinline__ void load_chunk(int c, uint32_t sb, int tid, int m0, int n0) {
    const int seg = c >> 4;                      // 0: q1.p1, 1: q1.p2, 2: q2.p1
    const int kb  = (c & 15) << 7;               // 128 bytes per chunk
    const int8_t* Ag = g_A8[seg == 2 ? 1 : 0] + (size_t)m0 * IN_DIM + kb;
    const int8_t* Bg = g_W8[seg == 1 ? 1 : 0] + (size_t)n0 * IN_DIM + kb;
#pragma unroll
    for (int t = 0; t < 12; ++t) {
        int idx = tid + t * 256;
        if (idx < 1024) {                               // A: 1024 x 16B
            int r = idx >> 3, c16 = idx & 7;
            cpa16(sb + SWZ(r * 128 + c16 * 16), Ag + (size_t)r * IN_DIM + c16 * 16);
        } else {                                        // B: 2048 x 16B
            int j = idx - 1024;
            int r = j >> 3, c16 = j & 7;
            cpa16(sb + A_BYTES + SWZ(r * 128 + c16 * 16), Bg + (size_t)r * IN_DIM + c16 * 16);
        }
    }
}

__global__ __launch_bounds__(256, 1) void gemm_imma_kernel(float* __restrict__ C) {
    extern __shared__ char smem_raw[];
    const uint32_t s0 = smem_u32(smem_raw);
    const int tid = threadIdx.x;
    const int wid = tid >> 5, lane = tid & 31;
    const int warp_m = wid & 1, warp_n = wid >> 1;     // 2m x 4n
    const int m0 = blockIdx.y * 128;
    const int n0 = blockIdx.x * 256;

    // ldmatrix addressing identical to the bf16 kernel (byte-compatible layouts)
    const int lrow = lane & 7;
    const int lt = lane >> 3;
    const uint32_t xo = (uint32_t)(lrow * 16);
    const int ra0 = warp_m * 64 + (lt & 1) * 8 + lrow;
    const int rb0 = warp_n * 64 + (lt & 1) * 8 + lrow;
    const uint32_t a_pre0 = (uint32_t)(ra0 * 128) | xo;
    const uint32_t b_pre0 = (uint32_t)(rb0 * 128) | xo;
    const uint32_t kbase = (lt >> 1) * 16;

    int acc[4][8][4];
#pragma unroll
    for (int i = 0; i < 4; ++i)
#pragma unroll
        for (int j = 0; j < 8; ++j)
#pragma unroll
            for (int q = 0; q < 4; ++q) acc[i][j][q] = 0;

    uint32_t af[2][4][4], bf[2][4][4];

#define LD_FRAGS(B, Asb_, Bsb_, kof_) do {                          \
        const uint32_t _ax = (Asb_) + (a_pre0 ^ (uint32_t)(kof_));  \
        const uint32_t _bx = (Bsb_) + (b_pre0 ^ (uint32_t)(kof_));  \
        ldm4(af[B][0], _ax);                                        \
        ldm4(af[B][1], _ax + 2048);                                 \
        ldm4(af[B][2], _ax + 4096);                                 \
        ldm4(af[B][3], _ax + 6144);                                 \
        ldm4(bf[B][0], _bx);                                        \
        ldm4(bf[B][1], _bx + 2048);                                 \
        ldm4(bf[B][2], _bx + 4096);                                 \
        ldm4(bf[B][3], _bx + 6144);                                 \
    } while (0)

#define DO_MMA(B) do {                                                  \
        _Pragma("unroll")                                               \
        for (int mt = 0; mt < 4; ++mt)                                  \
            _Pragma("unroll")                                           \
            for (int np = 0; np < 4; ++np) {                            \
                mma_s8(acc[mt][2 * np + 0], af[B][mt], bf[B][np][0], bf[B][np][2]); \
                mma_s8(acc[mt][2 * np + 1], af[B][mt], bf[B][np][1], bf[B][np][3]); \
            }                                                           \
    } while (0)

    // prologue: fill both stages
    load_chunk(0, s0, tid, m0, n0);
    asm volatile("cp.async.commit_group;" ::: "memory");
    load_chunk(1, s0 + STG_B, tid, m0, n0);
    asm volatile("cp.async.commit_group;" ::: "memory");
    asm volatile("cp.async.wait_group 1;" ::: "memory");
    __syncthreads();
    LD_FRAGS(0, s0, s0 + A_BYTES, kbase);

    for (int c = 0; c < NCHUNK; ++c) {
        // all committed groups complete -> chunk c (and c+1 if issued) resident
        asm volatile("cp.async.wait_group 0;" ::: "memory");
        __syncthreads();

        const uint32_t sb = s0 + (c & 1) * STG_B;
        const uint32_t Asb = sb, Bsb = sb + A_BYTES;
#pragma unroll
        for (int ks = 0; ks < 4; ++ks) {                 // 4 x k32 per chunk
            const int cb = ks & 1;
            if (ks < 3) {
                LD_FRAGS(cb ^ 1, Asb, Bsb, (ks + 1) * 32 + kbase);
            } else if (c + 1 < NCHUNK) {
                const uint32_t sbn = s0 + ((c + 1) & 1) * STG_B;
                LD_FRAGS(cb ^ 1, sbn, sbn + A_BYTES, kbase);
            }
            DO_MMA(cb);
        }

        // phase boundary: spill S1 (q1.p1) to smem as fp32, reset accumulators
        if (c == 15) {
#pragma unroll
            for (int mt = 0; mt < 4; ++mt)
#pragma unroll
                for (int nt = 0; nt < 8; ++nt) {
                    const int g = mt * 8 + nt;
                    float4 f;
                    f.x = (float)acc[mt][nt][0];
                    f.y = (float)acc[mt][nt][1];
                    f.z = (float)acc[mt][nt][2];
                    f.w = (float)acc[mt][nt][3];
                    *(float4*)(smem_raw + SPILL_OFF + g * 4096 + tid * 16) = f;
                    acc[mt][nt][0] = 0; acc[mt][nt][1] = 0;
                    acc[mt][nt][2] = 0; acc[mt][nt][3] = 0;
                }
        }

        __syncthreads();                                  // all reads of buf(c) done
        if (c + 2 < NCHUNK) {
            load_chunk(c + 2, sb, tid, m0, n0);           // reuse buffer of chunk c
        }
        asm volatile("cp.async.commit_group;" ::: "memory");
    }

    // ---- epilogue: out = tanh(alpha*beta*(S1 + S2/254) + add) ----
    const int g = lane >> 2, tig = lane & 3;
    const float inv254 = 1.0f / 254.0f;
#pragma unroll
    for (int mt = 0; mt < 4; ++mt) {
        const int r0 = m0 + warp_m * 64 + mt * 16 + g;
        const float al0 = g_sa[r0], al1 = g_sa[r0 + 8];
#pragma unroll
        for (int nt = 0; nt < 8; ++nt) {
            const int col = n0 + warp_n * 64 + nt * 8 + tig * 2;
            const float b0 = g_sb[col], b1 = g_sb[col + 1];
            const float a0 = __ldg(&g_add[col]);
            const float a1 = __ldg(&g_add[col + 1]);
            float4 f = *(const float4*)(smem_raw + SPILL_OFF + (mt * 8 + nt) * 4096 + tid * 16);
            float2 o0, o1;
            o0.x = tanh_apx(fmaf(al0 * b0, fmaf((float)acc[mt][nt][0], inv254, f.x), a0));
            o0.y = tanh_apx(fmaf(al0 * b1, fmaf((float)acc[mt][nt][1], inv254, f.y), a1));
            o1.x = tanh_apx(fmaf(al1 * b0, fmaf((float)acc[mt][nt][2], inv254, f.z), a0));
            o1.y = tanh_apx(fmaf(al1 * b1, fmaf((float)acc[mt][nt][3], inv254, f.w), a1));
            *(float2*)(C + (size_t)r0 * OUT_DIM + col) = o0;
            *(float2*)(C + (size_t)(r0 + 8) * OUT_DIM + col) = o1;
        }
    }
}

// ---------------- launch ----------------
#define GEMM_SMEM (2 * STG_B + 256 * 128 * 4)    // 96 KB stages + 128 KB spill = 224 KB

extern "C" void kernel_launch(void* const* d_in, const int* in_sizes, int n_in,
                              void* d_out, int out_size) {
    const float* x   = (const float*)d_in[0];  // [8192, 2048]
    const float* hdw = (const float*)d_in[1];  // [5, 2048, 2048]
    const float* W   = (const float*)d_in[2];  // [2048, 2048]
    const float* b   = (const float*)d_in[3];  // [2048]
    float* out = (float*)d_out;                // [8192, 2048]

    cudaFuncSetAttribute(gemm_imma_kernel, cudaFuncAttributeMaxDynamicSharedMemorySize, GEMM_SMEM);

    quant_a_kernel<<<BATCH / 8, 256>>>(x);
    colmax_w_kernel<<<OUT_DIM / 256, 256>>>(W);
    quant_w_kernel<<<dim3(OUT_DIM / 32, IN_DIM / 128), 256>>>(W);
    hd_bias_kernel<<<OUT_DIM / 256, 256>>>(hdw, b);

    dim3 grid(OUT_DIM / 256, BATCH / 128);     // (8, 64) = 512 CTAs
    gemm_imma_kernel<<<grid, 256, GEMM_SMEM>>>(out);
}

// round 14
// speedup vs baseline: 3.7550x; 3.7550x over previous
#include <cuda_runtime.h>
#include <cuda_bf16.h>
#include <stdint.h>

#define BATCH   8192
#define IN_DIM  2048
#define OUT_DIM 2048
#define DEPTH   5

// ---------------- device scratch (no allocs allowed) ----------------
__device__ __nv_bfloat16 g_A2[(size_t)2 * BATCH * IN_DIM];    // rows 0..8191 = hi(x), 8192.. = lo(x)
__device__ __nv_bfloat16 g_W2[(size_t)2 * OUT_DIM * IN_DIM];  // rows n = hi(W^T), 2048+n = lo(W^T)
__device__ float g_add[OUT_DIM];                              // bias + hd

// ---------------- PTX helpers (family-stable only) ----------------
__device__ __forceinline__ uint32_t smem_u32(const void* p) {
    uint32_t a;
    asm("{ .reg .u64 t; cvta.to.shared.u64 t, %1; cvt.u32.u64 %0, t; }" : "=r"(a) : "l"(p));
    return a;
}
__device__ __forceinline__ void cpa16(uint32_t s, const void* g) {
    asm volatile("cp.async.cg.shared.global [%0], [%1], 16;" :: "r"(s), "l"(g));
}
__device__ __forceinline__ void ldm4(uint32_t* r, uint32_t addr) {
    asm volatile("ldmatrix.sync.aligned.m8n8.x4.shared.b16 {%0,%1,%2,%3}, [%4];"
                 : "=r"(r[0]), "=r"(r[1]), "=r"(r[2]), "=r"(r[3]) : "r"(addr));
}
__device__ __forceinline__ void mma_bf16(float* c, const uint32_t* a, uint32_t b0, uint32_t b1) {
    asm volatile(
        "mma.sync.aligned.m16n8k16.row.col.f32.bf16.bf16.f32 "
        "{%0,%1,%2,%3}, {%4,%5,%6,%7}, {%8,%9}, {%0,%1,%2,%3};"
        : "+f"(c[0]), "+f"(c[1]), "+f"(c[2]), "+f"(c[3])
        : "r"(a[0]), "r"(a[1]), "r"(a[2]), "r"(a[3]), "r"(b0), "r"(b1));
}
__device__ __forceinline__ float tanh_apx(float x) {
    float y;
    asm("tanh.approx.f32 %0, %1;" : "=f"(y) : "f"(x));
    return y;
}
#define SWZ(o) ((o) ^ (((o) >> 3) & 0x70))

// ---------------- prepass kernels ----------------
__global__ void conv_a_kernel(const float* __restrict__ x) {
    size_t i = (size_t)blockIdx.x * blockDim.x + threadIdx.x;  // over 4.19M float4
    float4 v = ((const float4*)x)[i];
    __nv_bfloat16 h0 = __float2bfloat16(v.x), h1 = __float2bfloat16(v.y);
    __nv_bfloat16 h2 = __float2bfloat16(v.z), h3 = __float2bfloat16(v.w);
    __nv_bfloat16 l0 = __float2bfloat16(v.x - __bfloat162float(h0));
    __nv_bfloat16 l1 = __float2bfloat16(v.y - __bfloat162float(h1));
    __nv_bfloat16 l2 = __float2bfloat16(v.z - __bfloat162float(h2));
    __nv_bfloat16 l3 = __float2bfloat16(v.w - __bfloat162float(h3));
    __nv_bfloat162* Ah = (__nv_bfloat162*)g_A2;
    __nv_bfloat162* Al = (__nv_bfloat162*)(g_A2 + (size_t)BATCH * IN_DIM);
    __nv_bfloat162 p;
    p.x = h0; p.y = h1; Ah[i * 2 + 0] = p;
    p.x = h2; p.y = h3; Ah[i * 2 + 1] = p;
    p.x = l0; p.y = l1; Al[i * 2 + 0] = p;
    p.x = l2; p.y = l3; Al[i * 2 + 1] = p;
}

__global__ void conv_w_kernel(const float* __restrict__ W) {  // W:[IN_DIM][OUT_DIM] -> W^T hi/lo
    __shared__ float t[32][33];
    int bx = blockIdx.x * 32, by = blockIdx.y * 32;
    int tx = threadIdx.x, ty = threadIdx.y;
#pragma unroll
    for (int j = 0; j < 32; j += 8)
        t[ty + j][tx] = W[(size_t)(by + ty + j) * OUT_DIM + bx + tx];
    __syncthreads();
#pragma unroll
    for (int j = 0; j < 32; j += 8) {
        float v = t[tx][ty + j];                 // = W[by+tx][bx+ty+j]
        size_t n = bx + ty + j, k = by + tx;
        __nv_bfloat16 h = __float2bfloat16(v);
        __nv_bfloat16 l = __float2bfloat16(v - __bfloat162float(h));
        g_W2[n * IN_DIM + k] = h;
        g_W2[(OUT_DIM + n) * IN_DIM + k] = l;
    }
}

__global__ void hd_bias_kernel(const float* __restrict__ hdw, const float* __restrict__ bias) {
    int o = blockIdx.x * blockDim.x + threadIdx.x;
    if (o < OUT_DIM) {
        float p = 1.0f;
#pragma unroll
        for (int d = 0; d < DEPTH; ++d)
            p *= cosf(hdw[(size_t)d * IN_DIM * OUT_DIM + (size_t)o * OUT_DIM]);
        g_add[o] = bias[o] + p * p * (1.0f / (float)IN_DIM);
    }
}

// ---------------- mma.sync GEMM ----------------
// CTA tile M=128 x N=128, 4 warps (2m x 2n) of 64x64, fragment double-buffered.
// ~250 regs/thread x 128 threads = 32K regs -> 2 CTAs/SM: cross-CTA overlap
// hides syncs, cp.async bursts and the wait_group-0 latency exposure.
// 3-stage cp.async pipeline (96 KB/CTA, 192 KB/SM). K'=6144 -> 96 chunks.
#define A_BYTES  (128 * 128)                     // 16 KB
#define B_BYTES  (128 * 128)                     // 16 KB
#define STG_B    (A_BYTES + B_BYTES)             // 32 KB
#define NCHUNK   96
#define NSTAGE   3
#define NT       128

__device__ __forceinline__ void load_chunk(int c, uint32_t sb, int tid, int m0, int n0) {
    int seg = c >> 5;                    // 0: hi*hi, 1: hi*lo, 2: lo*hi
    int kb  = (c & 31) << 6;
    size_t arow = (seg == 2 ? (size_t)BATCH : 0) + m0;
    size_t brow = (seg == 1 ? (size_t)OUT_DIM : 0) + n0;
    const __nv_bfloat16* Ag = g_A2 + arow * IN_DIM + kb;
    const __nv_bfloat16* Bg = g_W2 + brow * IN_DIM + kb;
#pragma unroll
    for (int t = 0; t < 16; ++t) {
        int idx = tid + t * NT;
        if (idx < 1024) {                               // A: 1024 x 16B
            int r = idx >> 3, c16 = idx & 7;
            cpa16(sb + SWZ(r * 128 + c16 * 16), Ag + (size_t)r * IN_DIM + c16 * 8);
        } else {                                        // B: 1024 x 16B
            int j = idx - 1024;
            int r = j >> 3, c16 = j & 7;
            cpa16(sb + A_BYTES + SWZ(r * 128 + c16 * 16), Bg + (size_t)r * IN_DIM + c16 * 8);
        }
    }
}

__global__ __launch_bounds__(NT, 2) void gemm_mma_kernel(float* __restrict__ C) {
    extern __shared__ char smem_raw[];
    const uint32_t s0 = smem_u32(smem_raw);            // dynamic smem is 1024-aligned
    const int tid = threadIdx.x;
    const int wid = tid >> 5, lane = tid & 31;
    const int warp_m = wid & 1, warp_n = wid >> 1;     // 2m x 2n of 64x64
    const int m0 = blockIdx.y * 128;
    const int n0 = blockIdx.x * 128;

    // XOR-folded ldmatrix addressing: swizzle xor depends only on lane&7,
    // row-tile steps (+16 rows) are +2048 B constants folded into immediates.
    const int lrow = lane & 7;
    const int lt = lane >> 3;
    const uint32_t xo = (uint32_t)(lrow * 16);
    const int ra0 = warp_m * 64 + (lt & 1) * 8 + lrow;
    const int rb0 = warp_n * 64 + (lt & 1) * 8 + lrow;
    const uint32_t a_pre0 = (uint32_t)(ra0 * 128) | xo;
    const uint32_t b_pre0 = (uint32_t)(rb0 * 128) | xo;
    const uint32_t kbase = (lt >> 1) * 16;             // 16B half-select within k16

    float acc[4][8][4];
#pragma unroll
    for (int i = 0; i < 4; ++i)
#pragma unroll
        for (int j = 0; j < 8; ++j)
#pragma unroll
            for (int q = 0; q < 4; ++q) acc[i][j][q] = 0.0f;

    uint32_t af[2][4][4], bf[2][4][4];

#define LD_FRAGS(B, Asb_, Bsb_, kof_) do {                          \
        const uint32_t _ax = (Asb_) + (a_pre0 ^ (uint32_t)(kof_));  \
        const uint32_t _bx = (Bsb_) + (b_pre0 ^ (uint32_t)(kof_));  \
        ldm4(af[B][0], _ax);                                        \
        ldm4(af[B][1], _ax + 2048);                                 \
        ldm4(af[B][2], _ax + 4096);                                 \
        ldm4(af[B][3], _ax + 6144);                                 \
        ldm4(bf[B][0], _bx);                                        \
        ldm4(bf[B][1], _bx + 2048);                                 \
        ldm4(bf[B][2], _bx + 4096);                                 \
        ldm4(bf[B][3], _bx + 6144);                                 \
    } while (0)

#define DO_MMA(B) do {                                                  \
        _Pragma("unroll")                                               \
        for (int mt = 0; mt < 4; ++mt)                                  \
            _Pragma("unroll")                                           \
            for (int np = 0; np < 4; ++np) {                            \
                mma_bf16(acc[mt][2 * np + 0], af[B][mt], bf[B][np][0], bf[B][np][2]); \
                mma_bf16(acc[mt][2 * np + 1], af[B][mt], bf[B][np][1], bf[B][np][3]); \
            }                                                           \
    } while (0)

    // prologue: fill 2 stages, preload chunk 0's first fragments
    load_chunk(0, s0, tid, m0, n0);
    asm volatile("cp.async.commit_group;" ::: "memory");
    load_chunk(1, s0 + STG_B, tid, m0, n0);
    asm volatile("cp.async.commit_group;" ::: "memory");
    asm volatile("cp.async.wait_group 1;" ::: "memory");
    __syncthreads();
    LD_FRAGS(0, s0, s0 + A_BYTES, kbase);

    uint32_t buf = 0, bnext = 1;                       // c%3, (c+1)%3
    for (int c = 0; c < NCHUNK; ++c) {
        // all committed groups (chunks <= c+1) complete; c+2 committed below
        asm volatile("cp.async.wait_group 0;" ::: "memory");
        __syncthreads();

        if (c + 2 < NCHUNK) {
            uint32_t b2 = bnext + 1; if (b2 == NSTAGE) b2 = 0;   // (c+2)%3
            load_chunk(c + 2, s0 + b2 * STG_B, tid, m0, n0);
        }
        asm volatile("cp.async.commit_group;" ::: "memory");

        const uint32_t Asb = s0 + buf * STG_B;
        const uint32_t Bsb = Asb + A_BYTES;
#pragma unroll
        for (int ks = 0; ks < 4; ++ks) {
            const int cb = ks & 1;
            if (ks < 3) {
                LD_FRAGS(cb ^ 1, Asb, Bsb, (ks + 1) * 32 + kbase);
            } else if (c + 1 < NCHUNK) {
                const uint32_t sbn = s0 + bnext * STG_B;   // chunk c+1, resident
                LD_FRAGS(cb ^ 1, sbn, sbn + A_BYTES, kbase);
            }
            DO_MMA(cb);
        }
        buf = bnext;
        if (++bnext == NSTAGE) bnext = 0;
    }

    // ---- epilogue: out = tanh(acc + bias + hd), direct fragment stores ----
    const int g = lane >> 2, tig = lane & 3;
#pragma unroll
    for (int mt = 0; mt < 4; ++mt) {
        const int r0 = m0 + warp_m * 64 + mt * 16 + g;
#pragma unroll
        for (int nt = 0; nt < 8; ++nt) {
            const int col = n0 + warp_n * 64 + nt * 8 + tig * 2;
            const float a0 = __ldg(&g_add[col]);
            const float a1 = __ldg(&g_add[col + 1]);
            float2 o0, o1;
            o0.x = tanh_apx(acc[mt][nt][0] + a0);
            o0.y = tanh_apx(acc[mt][nt][1] + a1);
            o1.x = tanh_apx(acc[mt][nt][2] + a0);
            o1.y = tanh_apx(acc[mt][nt][3] + a1);
            *(float2*)(C + (size_t)r0 * OUT_DIM + col) = o0;
            *(float2*)(C + (size_t)(r0 + 8) * OUT_DIM + col) = o1;
        }
    }
}

// ---------------- launch ----------------
#define GEMM_SMEM (NSTAGE * STG_B)   // 96 KB per CTA, 2 CTAs/SM

extern "C" void kernel_launch(void* const* d_in, const int* in_sizes, int n_in,
                              void* d_out, int out_size) {
    const float* x   = (const float*)d_in[0];  // [8192, 2048]
    const float* hdw = (const float*)d_in[1];  // [5, 2048, 2048]
    const float* W   = (const float*)d_in[2];  // [2048, 2048]
    const float* b   = (const float*)d_in[3];  // [2048]
    float* out = (float*)d_out;                // [8192, 2048]

    cudaFuncSetAttribute(gemm_mma_kernel, cudaFuncAttributeMaxDynamicSharedMemorySize, GEMM_SMEM);

    conv_a_kernel<<<(BATCH * IN_DIM / 4) / 256, 256>>>(x);
    conv_w_kernel<<<dim3(OUT_DIM / 32, IN_DIM / 32), dim3(32, 8)>>>(W);
    hd_bias_kernel<<<OUT_DIM / 256, 256>>>(hdw, b);

    dim3 grid(OUT_DIM / 128, BATCH / 128);     // (16, 64) = 1024 CTAs
    gemm_mma_kernel<<<grid, NT, GEMM_SMEM>>>(out);
}

// round 16
// speedup vs baseline: 3.7793x; 1.0065x over previous
#include <cuda_runtime.h>
#include <cuda_bf16.h>
#include <stdint.h>

#define BATCH   8192
#define IN_DIM  2048
#define OUT_DIM 2048
#define DEPTH   5

// Tile bookkeeping: 1024 tiles of 128x128. First N_FULL run full-K (3 clean
// waves at 2 CTAs/SM x 152 SMs = 304 slots); the last NSPLIT tiles are split
// into two half-K CTAs each (launched last -> half-duration 4th wave).
#define N_TILES  1024
#define N_FULL   912
#define NSPLIT   (N_TILES - N_FULL)      // 112
#define GRID     (N_FULL + 2 * NSPLIT)   // 1136

// ---------------- device scratch (no allocs allowed) ----------------
__device__ __nv_bfloat16 g_A2[(size_t)2 * BATCH * IN_DIM];    // rows 0..8191 = hi(x), 8192.. = lo(x)
__device__ __nv_bfloat16 g_W2[(size_t)2 * OUT_DIM * IN_DIM];  // rows n = hi(W^T), 2048+n = lo(W^T)
__device__ float g_add[OUT_DIM];                              // bias + hd
__device__ float g_part[2][(size_t)NSPLIT * 128 * 128];       // split-K partials

// ---------------- PTX helpers (family-stable only) ----------------
__device__ __forceinline__ uint32_t smem_u32(const void* p) {
    uint32_t a;
    asm("{ .reg .u64 t; cvta.to.shared.u64 t, %1; cvt.u32.u64 %0, t; }" : "=r"(a) : "l"(p));
    return a;
}
__device__ __forceinline__ void cpa16(uint32_t s, const void* g) {
    asm volatile("cp.async.cg.shared.global [%0], [%1], 16;" :: "r"(s), "l"(g));
}
__device__ __forceinline__ void ldm4(uint32_t* r, uint32_t addr) {
    asm volatile("ldmatrix.sync.aligned.m8n8.x4.shared.b16 {%0,%1,%2,%3}, [%4];"
                 : "=r"(r[0]), "=r"(r[1]), "=r"(r[2]), "=r"(r[3]) : "r"(addr));
}
__device__ __forceinline__ void mma_bf16(float* c, const uint32_t* a, uint32_t b0, uint32_t b1) {
    asm volatile(
        "mma.sync.aligned.m16n8k16.row.col.f32.bf16.bf16.f32 "
        "{%0,%1,%2,%3}, {%4,%5,%6,%7}, {%8,%9}, {%0,%1,%2,%3};"
        : "+f"(c[0]), "+f"(c[1]), "+f"(c[2]), "+f"(c[3])
        : "r"(a[0]), "r"(a[1]), "r"(a[2]), "r"(a[3]), "r"(b0), "r"(b1));
}
__device__ __forceinline__ float tanh_apx(float x) {
    float y;
    asm("tanh.approx.f32 %0, %1;" : "=f"(y) : "f"(x));
    return y;
}
#define SWZ(o) ((o) ^ (((o) >> 3) & 0x70))

// ---------------- prepass kernels ----------------
__global__ void conv_a_kernel(const float* __restrict__ x) {
    size_t i = (size_t)blockIdx.x * blockDim.x + threadIdx.x;  // over 4.19M float4
    float4 v = ((const float4*)x)[i];
    __nv_bfloat16 h0 = __float2bfloat16(v.x), h1 = __float2bfloat16(v.y);
    __nv_bfloat16 h2 = __float2bfloat16(v.z), h3 = __float2bfloat16(v.w);
    __nv_bfloat16 l0 = __float2bfloat16(v.x - __bfloat162float(h0));
    __nv_bfloat16 l1 = __float2bfloat16(v.y - __bfloat162float(h1));
    __nv_bfloat16 l2 = __float2bfloat16(v.z - __bfloat162float(h2));
    __nv_bfloat16 l3 = __float2bfloat16(v.w - __bfloat162float(h3));
    __nv_bfloat162* Ah = (__nv_bfloat162*)g_A2;
    __nv_bfloat162* Al = (__nv_bfloat162*)(g_A2 + (size_t)BATCH * IN_DIM);
    __nv_bfloat162 p;
    p.x = h0; p.y = h1; Ah[i * 2 + 0] = p;
    p.x = h2; p.y = h3; Ah[i * 2 + 1] = p;
    p.x = l0; p.y = l1; Al[i * 2 + 0] = p;
    p.x = l2; p.y = l3; Al[i * 2 + 1] = p;
}

__global__ void conv_w_kernel(const float* __restrict__ W) {  // W:[IN_DIM][OUT_DIM] -> W^T hi/lo
    __shared__ float t[32][33];
    int bx = blockIdx.x * 32, by = blockIdx.y * 32;
    int tx = threadIdx.x, ty = threadIdx.y;
#pragma unroll
    for (int j = 0; j < 32; j += 8)
        t[ty + j][tx] = W[(size_t)(by + ty + j) * OUT_DIM + bx + tx];
    __syncthreads();
#pragma unroll
    for (int j = 0; j < 32; j += 8) {
        float v = t[tx][ty + j];                 // = W[by+tx][bx+ty+j]
        size_t n = bx + ty + j, k = by + tx;
        __nv_bfloat16 h = __float2bfloat16(v);
        __nv_bfloat16 l = __float2bfloat16(v - __bfloat162float(h));
        g_W2[n * IN_DIM + k] = h;
        g_W2[(OUT_DIM + n) * IN_DIM + k] = l;
    }
}

__global__ void hd_bias_kernel(const float* __restrict__ hdw, const float* __restrict__ bias) {
    int o = blockIdx.x * blockDim.x + threadIdx.x;
    if (o < OUT_DIM) {
        float p = 1.0f;
#pragma unroll
        for (int d = 0; d < DEPTH; ++d)
            p *= cosf(hdw[(size_t)d * IN_DIM * OUT_DIM + (size_t)o * OUT_DIM]);
        g_add[o] = bias[o] + p * p * (1.0f / (float)IN_DIM);
    }
}

// ---------------- mma.sync GEMM ----------------
// CTA tile M=128 x N=128, 4 warps (2m x 2n) of 64x64, fragment double-buffered,
// 3-stage cp.async pipeline, 2 CTAs/SM. K'=6144 -> 96 chunks (full) or 48 (split).
#define A_BYTES  (128 * 128)                     // 16 KB
#define B_BYTES  (128 * 128)                     // 16 KB
#define STG_B    (A_BYTES + B_BYTES)             // 32 KB
#define NSTAGE   3
#define NT       128

__device__ __forceinline__ void load_chunk(int c, uint32_t sb, int tid, int m0, int n0) {
    int seg = c >> 5;                    // 0: hi*hi, 1: hi*lo, 2: lo*hi
    int kb  = (c & 31) << 6;
    size_t arow = (seg == 2 ? (size_t)BATCH : 0) + m0;
    size_t brow = (seg == 1 ? (size_t)OUT_DIM : 0) + n0;
    const __nv_bfloat16* Ag = g_A2 + arow * IN_DIM + kb;
    const __nv_bfloat16* Bg = g_W2 + brow * IN_DIM + kb;
#pragma unroll
    for (int t = 0; t < 16; ++t) {
        int idx = tid + t * NT;
        if (idx < 1024) {                               // A: 1024 x 16B
            int r = idx >> 3, c16 = idx & 7;
            cpa16(sb + SWZ(r * 128 + c16 * 16), Ag + (size_t)r * IN_DIM + c16 * 8);
        } else {                                        // B: 1024 x 16B
            int j = idx - 1024;
            int r = j >> 3, c16 = j & 7;
            cpa16(sb + A_BYTES + SWZ(r * 128 + c16 * 16), Bg + (size_t)r * IN_DIM + c16 * 8);
        }
    }
}

__global__ __launch_bounds__(NT, 2) void gemm_mma_kernel(float* __restrict__ C) {
    extern __shared__ char smem_raw[];
    const uint32_t s0 = smem_u32(smem_raw);
    const int tid = threadIdx.x;
    const int wid = tid >> 5, lane = tid & 31;
    const int warp_m = wid & 1, warp_n = wid >> 1;     // 2m x 2n of 64x64
    const int bid = blockIdx.x;

    // tile / K-range assignment
    int tile, c_lo, c_hi;
    float* part = (float*)0;
    if (bid < N_FULL) {
        tile = bid; c_lo = 0; c_hi = 96;
    } else {
        const int j = bid - N_FULL;
        tile = N_FULL + (j >> 1);
        const int h = j & 1;
        c_lo = h * 48; c_hi = c_lo + 48;
        part = g_part[h] + (size_t)(tile - N_FULL) * (128 * 128);
    }
    const int m0 = (tile >> 4) * 128;
    const int n0 = (tile & 15) * 128;

    // XOR-folded ldmatrix addressing
    const int lrow = lane & 7;
    const int lt = lane >> 3;
    const uint32_t xo = (uint32_t)(lrow * 16);
    const int ra0 = warp_m * 64 + (lt & 1) * 8 + lrow;
    const int rb0 = warp_n * 64 + (lt & 1) * 8 + lrow;
    const uint32_t a_pre0 = (uint32_t)(ra0 * 128) | xo;
    const uint32_t b_pre0 = (uint32_t)(rb0 * 128) | xo;
    const uint32_t kbase = (lt >> 1) * 16;

    float acc[4][8][4];
#pragma unroll
    for (int i = 0; i < 4; ++i)
#pragma unroll
        for (int j = 0; j < 8; ++j)
#pragma unroll
            for (int q = 0; q < 4; ++q) acc[i][j][q] = 0.0f;

    uint32_t af[2][4][4], bf[2][4][4];

#define LD_FRAGS(B, Asb_, Bsb_, kof_) do {                          \
        const uint32_t _ax = (Asb_) + (a_pre0 ^ (uint32_t)(kof_));  \
        const uint32_t _bx = (Bsb_) + (b_pre0 ^ (uint32_t)(kof_));  \
        ldm4(af[B][0], _ax);                                        \
        ldm4(af[B][1], _ax + 2048);                                 \
        ldm4(af[B][2], _ax + 4096);                                 \
        ldm4(af[B][3], _ax + 6144);                                 \
        ldm4(bf[B][0], _bx);                                        \
        ldm4(bf[B][1], _bx + 2048);                                 \
        ldm4(bf[B][2], _bx + 4096);                                 \
        ldm4(bf[B][3], _bx + 6144);                                 \
    } while (0)

#define DO_MMA(B) do {                                                  \
        _Pragma("unroll")                                               \
        for (int mt = 0; mt < 4; ++mt)                                  \
            _Pragma("unroll")                                           \
            for (int np = 0; np < 4; ++np) {                            \
                mma_bf16(acc[mt][2 * np + 0], af[B][mt], bf[B][np][0], bf[B][np][2]); \
                mma_bf16(acc[mt][2 * np + 1], af[B][mt], bf[B][np][1], bf[B][np][3]); \
            }                                                           \
    } while (0)

    // prologue: fill 2 stages with chunks c_lo, c_lo+1; preload first frags
    load_chunk(c_lo, s0, tid, m0, n0);
    asm volatile("cp.async.commit_group;" ::: "memory");
    load_chunk(c_lo + 1, s0 + STG_B, tid, m0, n0);
    asm volatile("cp.async.commit_group;" ::: "memory");
    asm volatile("cp.async.wait_group 1;" ::: "memory");
    __syncthreads();
    LD_FRAGS(0, s0, s0 + A_BYTES, kbase);

    uint32_t buf = 0, bnext = 1;
    for (int c = c_lo; c < c_hi; ++c) {
        asm volatile("cp.async.wait_group 0;" ::: "memory");
        __syncthreads();

        if (c + 2 < c_hi) {
            uint32_t b2 = bnext + 1; if (b2 == NSTAGE) b2 = 0;
            load_chunk(c + 2, s0 + b2 * STG_B, tid, m0, n0);
        }
        asm volatile("cp.async.commit_group;" ::: "memory");

        const uint32_t Asb = s0 + buf * STG_B;
        const uint32_t Bsb = Asb + A_BYTES;
#pragma unroll
        for (int ks = 0; ks < 4; ++ks) {
            const int cb = ks & 1;
            if (ks < 3) {
                LD_FRAGS(cb ^ 1, Asb, Bsb, (ks + 1) * 32 + kbase);
            } else if (c + 1 < c_hi) {
                const uint32_t sbn = s0 + bnext * STG_B;
                LD_FRAGS(cb ^ 1, sbn, sbn + A_BYTES, kbase);
            }
            DO_MMA(cb);
        }
        buf = bnext;
        if (++bnext == NSTAGE) bnext = 0;
    }

    // ---- epilogue ----
    const int g = lane >> 2, tig = lane & 3;
    if (part) {
        // split-K: store raw fp32 partials, tile-local 128x128 row-major
#pragma unroll
        for (int mt = 0; mt < 4; ++mt) {
            const int rl = warp_m * 64 + mt * 16 + g;
#pragma unroll
            for (int nt = 0; nt < 8; ++nt) {
                const int cl = warp_n * 64 + nt * 8 + tig * 2;
                float2 p0, p1;
                p0.x = acc[mt][nt][0]; p0.y = acc[mt][nt][1];
                p1.x = acc[mt][nt][2]; p1.y = acc[mt][nt][3];
                *(float2*)(part + rl * 128 + cl) = p0;
                *(float2*)(part + (rl + 8) * 128 + cl) = p1;
            }
        }
    } else {
#pragma unroll
        for (int mt = 0; mt < 4; ++mt) {
            const int r0 = m0 + warp_m * 64 + mt * 16 + g;
#pragma unroll
            for (int nt = 0; nt < 8; ++nt) {
                const int col = n0 + warp_n * 64 + nt * 8 + tig * 2;
                const float a0 = __ldg(&g_add[col]);
                const float a1 = __ldg(&g_add[col + 1]);
                float2 o0, o1;
                o0.x = tanh_apx(acc[mt][nt][0] + a0);
                o0.y = tanh_apx(acc[mt][nt][1] + a1);
                o1.x = tanh_apx(acc[mt][nt][2] + a0);
                o1.y = tanh_apx(acc[mt][nt][3] + a1);
                *(float2*)(C + (size_t)r0 * OUT_DIM + col) = o0;
                *(float2*)(C + (size_t)(r0 + 8) * OUT_DIM + col) = o1;
            }
        }
    }
}

// ---------------- merge kernel for split tiles ----------------
__global__ void merge_kernel(float* __restrict__ C) {
    const size_t i = (size_t)blockIdx.x * blockDim.x + threadIdx.x;  // over NSPLIT*16384/4
    float4 p0 = ((const float4*)g_part[0])[i];
    float4 p1 = ((const float4*)g_part[1])[i];
    const size_t e = i * 4;
    const int tile = N_FULL + (int)(e >> 14);
    const int within = (int)(e & 16383);
    const int row = within >> 7, col = within & 127;
    const int m = (tile >> 4) * 128 + row;
    const int n = (tile & 15) * 128 + col;
    float4 o;
    o.x = tanh_apx(p0.x + p1.x + g_add[n + 0]);
    o.y = tanh_apx(p0.y + p1.y + g_add[n + 1]);
    o.z = tanh_apx(p0.z + p1.z + g_add[n + 2]);
    o.w = tanh_apx(p0.w + p1.w + g_add[n + 3]);
    *(float4*)(C + (size_t)m * OUT_DIM + n) = o;
}

// ---------------- launch ----------------
#define GEMM_SMEM (NSTAGE * STG_B)   // 96 KB per CTA, 2 CTAs/SM

extern "C" void kernel_launch(void* const* d_in, const int* in_sizes, int n_in,
                              void* d_out, int out_size) {
    const float* x   = (const float*)d_in[0];  // [8192, 2048]
    const float* hdw = (const float*)d_in[1];  // [5, 2048, 2048]
    const float* W   = (const float*)d_in[2];  // [2048, 2048]
    const float* b   = (const float*)d_in[3];  // [2048]
    float* out = (float*)d_out;                // [8192, 2048]

    cudaFuncSetAttribute(gemm_mma_kernel, cudaFuncAttributeMaxDynamicSharedMemorySize, GEMM_SMEM);

    conv_a_kernel<<<(BATCH * IN_DIM / 4) / 256, 256>>>(x);
    conv_w_kernel<<<dim3(OUT_DIM / 32, IN_DIM / 32), dim3(32, 8)>>>(W);
    hd_bias_kernel<<<OUT_DIM / 256, 256>>>(hdw, b);

    gemm_mma_kernel<<<GRID, NT, GEMM_SMEM>>>(out);
    merge_kernel<<<(NSPLIT * 128 * 128 / 4) / 256, 256>>>(out);
}